// round 11
// baseline (speedup 1.0000x reference)
#include <cuda_runtime.h>
#include <cuda_bf16.h>
#include <cstdint>
#include <math.h>

// ---------------- problem constants ----------------
#define T     2048
#define HD    2048          // hidden
#define E     8             // routed experts
#define IM    1408          // moe intermediate
#define ISH   2816          // shared intermediate
#define BM    128
#define BK    64            // bf16 k elems per stage (=128B rows)
#define MAXP  (2*T + E*BM)  // 5120 padded pair rows
#define NTILES (MAXP/BM)    // 40

// gu stage smem layout (bytes)
#define GU_AH 0
#define GU_AL 16384
#define GU_GH 32768
#define GU_GL 40960
#define GU_UH 49152
#define GU_UL 57344
#define GU_STAGE 65536
// down stage layout
#define DN_AH 0
#define DN_AL 16384
#define DN_BH 32768
#define DN_BL 49152
#define DN_STAGE 65536
#define SMEM_BYTES (2*GU_STAGE)   // 131072 for both kernels

#define SMEM_SWIZZLE_128B(off) ((off) ^ (((off) >> 3) & 0x70))

__device__ __forceinline__ uint32_t smem_to_u32(const void* p) {
    uint32_t a;
    asm("{ .reg .u64 t; cvta.to.shared.u64 t, %1; cvt.u32.u64 %0, t; }" : "=r"(a) : "l"(p));
    return a;
}

#define CP_ASYNC16(dst_u32, src_ptr) \
    asm volatile("cp.async.cg.shared.global [%0], [%1], 16;" :: "r"(dst_u32), "l"(src_ptr))
#define CP_ASYNC_WAIT_ALL() asm volatile("cp.async.wait_all;" ::: "memory")

#define LDSM_X4(d0,d1,d2,d3,a) \
    asm volatile("ldmatrix.sync.aligned.m8n8.x4.shared.b16 {%0,%1,%2,%3}, [%4];" \
        : "=r"(d0), "=r"(d1), "=r"(d2), "=r"(d3) : "r"(a))

#define MMA16816(d, a, b0, b1) \
    asm volatile("mma.sync.aligned.m16n8k16.row.col.f32.bf16.bf16.f32 " \
        "{%0,%1,%2,%3}, {%4,%5,%6,%7}, {%8,%9}, {%0,%1,%2,%3};" \
        : "+f"((d)[0]), "+f"((d)[1]), "+f"((d)[2]), "+f"((d)[3]) \
        : "r"((a)[0]), "r"((a)[1]), "r"((a)[2]), "r"((a)[3]), "r"(b0), "r"(b1))

// fp32 -> bf16 hi/lo split of two consecutive values, packed bf16x2
__device__ __forceinline__ uint32_t pack2(float x, float y, uint32_t& lob) {
    __nv_bfloat162 h = __float22bfloat162_rn(make_float2(x, y));
    float2 hf = __bfloat1622float2(h);
    __nv_bfloat162 l = __float22bfloat162_rn(make_float2(x - hf.x, y - hf.y));
    lob = *reinterpret_cast<uint32_t*>(&l);
    return *reinterpret_cast<uint32_t*>(&h);
}

// convert two prefetched float4 (8 fp32) -> swizzled bf16 hi/lo 16B stores
__device__ __forceinline__ void cvt_store8_reg(float4 a, float4 b, char* hibase, char* lobase,
                                               int row, int c2)
{
    uint32_t l0, l1, l2, l3;
    uint32_t h0 = pack2(a.x, a.y, l0);
    uint32_t h1 = pack2(a.z, a.w, l1);
    uint32_t h2 = pack2(b.x, b.y, l2);
    uint32_t h3 = pack2(b.z, b.w, l3);
    uint32_t sw = SMEM_SWIZZLE_128B((uint32_t)(row * 128 + c2 * 8));
    *(uint4*)(hibase + sw) = make_uint4(h0, h1, h2, h3);
    *(uint4*)(lobase + sw) = make_uint4(l0, l1, l2, l3);
}

// ---------------- device scratch (static) ----------------
__device__ int   d_topk_idx[2*T];
__device__ float d_topk_w[2*T];
__device__ int   d_cnt[E];
__device__ int   d_off[E];
__device__ int   d_tile_e[NTILES];
__device__ int   d_ptok[MAXP];
__device__ float d_pw[MAXP];           // per-pair combine weight (0 on padding)
__device__ __nv_bfloat16 x_hi[(size_t)T*HD],    x_lo[(size_t)T*HD];
__device__ __nv_bfloat16 h_hi[(size_t)MAXP*IM], h_lo[(size_t)MAXP*IM];
__device__ __nv_bfloat16 sh_hi[(size_t)T*ISH],  sh_lo[(size_t)T*ISH];

// ---------------- split: fp32 -> bf16 hi + lo (x only) ----------------
__global__ void split_k(const float* __restrict__ s,
                        __nv_bfloat16* __restrict__ hi, __nv_bfloat16* __restrict__ lo,
                        size_t n4)
{
    size_t stride = (size_t)gridDim.x * blockDim.x;
    const float4* s4 = (const float4*)s;
    uint2* h2 = (uint2*)hi;
    uint2* l2 = (uint2*)lo;
    for (size_t i = (size_t)blockIdx.x * blockDim.x + threadIdx.x; i < n4; i += stride) {
        float4 v = s4[i];
        uint32_t l0, l1;
        uint32_t h0 = pack2(v.x, v.y, l0);
        uint32_t h1 = pack2(v.z, v.w, l1);
        h2[i] = make_uint2(h0, h1);
        l2[i] = make_uint2(l0, l1);
    }
}

// ---------------- router ----------------
__global__ void router_k(const float* __restrict__ x,
                         const float* __restrict__ rw,
                         const float* __restrict__ bias)
{
    __shared__ float xs[HD];
    __shared__ float logits[E];
    int t = blockIdx.x, tid = threadIdx.x;
    for (int i = tid; i < HD; i += blockDim.x) xs[i] = x[(size_t)t*HD + i];
    __syncthreads();
    int wid = tid >> 5, lane = tid & 31;
    if (wid < E) {
        float s = 0.f;
        for (int k = lane; k < HD; k += 32) s += xs[k] * rw[wid*HD + k];
        #pragma unroll
        for (int o = 16; o; o >>= 1) s += __shfl_down_sync(0xffffffffu, s, o);
        if (!lane) logits[wid] = s;
    }
    __syncthreads();
    if (tid == 0) {
        float sc[E], sfc[E];
        #pragma unroll
        for (int e = 0; e < E; e++) {
            sc[e]  = 1.f / (1.f + expf(-logits[e]));
            sfc[e] = sc[e] + bias[e];
        }
        float gs[4];
        #pragma unroll
        for (int g = 0; g < 4; g++) gs[g] = sfc[2*g] + sfc[2*g+1];
        int g1 = 0;
        #pragma unroll
        for (int g = 1; g < 4; g++) if (gs[g] > gs[g1]) g1 = g;
        int g2 = -1;
        #pragma unroll
        for (int g = 0; g < 4; g++) { if (g == g1) continue; if (g2 < 0 || gs[g] > gs[g2]) g2 = g; }
        float masked[E];
        #pragma unroll
        for (int e = 0; e < E; e++) { int g = e >> 1; masked[e] = (g == g1 || g == g2) ? sfc[e] : 0.f; }
        int i1 = 0;
        #pragma unroll
        for (int e = 1; e < E; e++) if (masked[e] > masked[i1]) i1 = e;
        int i2 = -1;
        #pragma unroll
        for (int e = 0; e < E; e++) { if (e == i1) continue; if (i2 < 0 || masked[e] > masked[i2]) i2 = e; }
        float w1 = sc[i1], w2 = sc[i2];
        float inv = 2.5f / (w1 + w2 + 1e-20f);
        d_topk_idx[2*t] = i1; d_topk_idx[2*t+1] = i2;
        d_topk_w[2*t]   = w1 * inv;
        d_topk_w[2*t+1] = w2 * inv;
    }
}

// ---------------- deterministic pair list ----------------
__global__ void build_pairs_k()
{
    __shared__ int cnts[E], offs[E];
    int tid = threadIdx.x, wid = tid >> 5, lane = tid & 31;
    for (int i = tid; i < MAXP; i += blockDim.x) { d_ptok[i] = 0; d_pw[i] = 0.f; }
    if (wid < E) {
        int c = 0;
        for (int base = 0; base < T; base += 32) {
            int t = base + lane;
            bool sel = (d_topk_idx[2*t] == wid) || (d_topk_idx[2*t+1] == wid);
            c += __popc(__ballot_sync(0xffffffffu, sel));
        }
        if (!lane) cnts[wid] = c;
    }
    __syncthreads();
    if (tid == 0) {
        int o = 0;
        for (int e = 0; e < E; e++) {
            offs[e] = o; d_off[e] = o; d_cnt[e] = cnts[e];
            o += ((cnts[e] + BM - 1) / BM) * BM;
        }
        int tcur = 0;
        for (int e = 0; e < E; e++) {
            int t0 = offs[e] / BM, nt = (cnts[e] + BM - 1) / BM;
            for (int i = 0; i < nt; i++) d_tile_e[t0 + i] = e;
            tcur = t0 + nt;
        }
        for (int i = tcur; i < NTILES; i++) d_tile_e[i] = -1;
    }
    __syncthreads();
    if (wid < E) {
        int pos = offs[wid];
        for (int base = 0; base < T; base += 32) {
            int t = base + lane;
            int e0 = d_topk_idx[2*t], e1 = d_topk_idx[2*t+1];
            int j = (e0 == wid) ? 0 : ((e1 == wid) ? 1 : -1);
            unsigned m = __ballot_sync(0xffffffffu, j >= 0);
            if (j >= 0) {
                int p = pos + __popc(m & ((1u << lane) - 1u));
                d_ptok[p] = t;
                d_pw[p]   = d_topk_w[2*t+j];
            }
            pos += __popc(m);
        }
    }
}

// ============ fused gate+up GEMM (mma.sync bf16 3-pass) + SwiGLU epilogue ============
// CTA 128x64 (x2 planes), K = HD. Fragment double-buffer pipelines LDSM ahead of MMA.
template<int ROUTED>
__global__ void __launch_bounds__(256)
gu_k(const __nv_bfloat16* __restrict__ Xh, const __nv_bfloat16* __restrict__ Xl,
     const float* __restrict__ Gw0, const float* __restrict__ Uw0,
     __nv_bfloat16* __restrict__ Chi, __nv_bfloat16* __restrict__ Clo)
{
    constexpr int NS  = HD / BK;            // 32
    constexpr int CLD = ROUTED ? IM : ISH;
    extern __shared__ char smem[];
    const uint32_t sb = smem_to_u32(smem);
    const int tid = threadIdx.x, wid = tid >> 5, lane = tid & 31;
    const int m0 = blockIdx.x * BM, n0 = blockIdx.y * 64;

    const float *gw = Gw0, *uw = Uw0;
    if (ROUTED) {
        int e = d_tile_e[blockIdx.x];
        if (e < 0) return;
        size_t eo = (size_t)e * IM * HD;
        gw += eo; uw += eo;
    }

    // A-plane cp.async descriptors
    const int rb  = tid >> 3;               // 0..31
    const int chB = (tid & 7) * 16;
    const int chE = (tid & 7) * 8;
    const __nv_bfloat16 *axh[4], *axl[4];
    uint32_t aswz[4];
    #pragma unroll
    for (int i = 0; i < 4; i++) {
        int r = rb + i * 32;
        int gr = m0 + r;
        int srow = ROUTED ? d_ptok[gr] : gr;
        aswz[i] = SMEM_SWIZZLE_128B((uint32_t)(r * 128 + chB));
        axh[i] = Xh + (size_t)srow * HD + chE;
        axl[i] = Xl + (size_t)srow * HD + chE;
    }
    // B-side (fp32 weights): 64 rows, 4 threads/row, 16 consecutive fp32 each
    const int brow_ld = tid >> 2;           // 0..63
    const int bc0     = (tid & 3) * 4;
    const float* gsrc = gw + (size_t)(n0 + brow_ld) * HD + bc0 * 4;
    const float* usrc = uw + (size_t)(n0 + brow_ld) * HD + bc0 * 4;

    auto issueA = [&](int s, int buf) {
        const uint32_t bs = sb + (uint32_t)buf * GU_STAGE;
        #pragma unroll
        for (int i = 0; i < 4; i++) {
            CP_ASYNC16(bs + GU_AH + aswz[i], axh[i] + s * BK);
            CP_ASYNC16(bs + GU_AL + aswz[i], axl[i] + s * BK);
        }
    };
    auto loadB = [&](int s, float4* pg, float4* pu) {
        const float4* g4 = (const float4*)(gsrc + s * BK);
        const float4* u4 = (const float4*)(usrc + s * BK);
        #pragma unroll
        for (int j = 0; j < 4; j++) { pg[j] = __ldg(g4 + j); pu[j] = __ldg(u4 + j); }
    };
    auto storeB = [&](int buf, const float4* pg, const float4* pu) {
        char* bb = smem + (size_t)buf * GU_STAGE;
        cvt_store8_reg(pg[0], pg[1], bb + GU_GH, bb + GU_GL, brow_ld, bc0);
        cvt_store8_reg(pg[2], pg[3], bb + GU_GH, bb + GU_GL, brow_ld, bc0 + 2);
        cvt_store8_reg(pu[0], pu[1], bb + GU_UH, bb + GU_UL, brow_ld, bc0);
        cvt_store8_reg(pu[2], pu[3], bb + GU_UH, bb + GU_UL, brow_ld, bc0 + 2);
    };

    // warp mapping: 4(m) x 2(n)
    const int mw = (wid & 3) * 32, nw = (wid >> 2) * 32;
    const int arow = mw + (lane & 15);
    const int acs  = lane >> 4;
    const int brow = nw + (lane & 7) + ((lane & 16) ? 8 : 0);
    const int bcs  = (lane >> 3) & 1;

    float accg[2][4][4] = {}, accu[2][4][4] = {};
    float4 pg[4], pu[4];

    // fragment double buffers
    uint32_t fah[2][2][4], fal[2][2][4];
    uint32_t fgh[2][8], fgl[2][8], fuh[2][8], ful[2][8];

    auto ldfrag = [&](uint32_t base, int k, int fb) {
        #pragma unroll
        for (int mt = 0; mt < 2; mt++) {
            uint32_t off = SMEM_SWIZZLE_128B((uint32_t)((arow + mt*16) * 128 + (2*k + acs) * 16));
            LDSM_X4(fah[fb][mt][0], fah[fb][mt][1], fah[fb][mt][2], fah[fb][mt][3], base + GU_AH + off);
            LDSM_X4(fal[fb][mt][0], fal[fb][mt][1], fal[fb][mt][2], fal[fb][mt][3], base + GU_AL + off);
        }
        uint32_t bo0 = SMEM_SWIZZLE_128B((uint32_t)(brow        * 128 + (2*k + bcs) * 16));
        uint32_t bo1 = SMEM_SWIZZLE_128B((uint32_t)((brow + 16) * 128 + (2*k + bcs) * 16));
        LDSM_X4(fgh[fb][0], fgh[fb][1], fgh[fb][2], fgh[fb][3], base + GU_GH + bo0);
        LDSM_X4(fgh[fb][4], fgh[fb][5], fgh[fb][6], fgh[fb][7], base + GU_GH + bo1);
        LDSM_X4(fgl[fb][0], fgl[fb][1], fgl[fb][2], fgl[fb][3], base + GU_GL + bo0);
        LDSM_X4(fgl[fb][4], fgl[fb][5], fgl[fb][6], fgl[fb][7], base + GU_GL + bo1);
        LDSM_X4(fuh[fb][0], fuh[fb][1], fuh[fb][2], fuh[fb][3], base + GU_UH + bo0);
        LDSM_X4(fuh[fb][4], fuh[fb][5], fuh[fb][6], fuh[fb][7], base + GU_UH + bo1);
        LDSM_X4(ful[fb][0], ful[fb][1], ful[fb][2], ful[fb][3], base + GU_UL + bo0);
        LDSM_X4(ful[fb][4], ful[fb][5], ful[fb][6], ful[fb][7], base + GU_UL + bo1);
    };
    auto mmafrag = [&](int fb) {
        #pragma unroll
        for (int mt = 0; mt < 2; mt++)
            #pragma unroll
            for (int nt = 0; nt < 4; nt++)
                MMA16816(accg[mt][nt], fah[fb][mt], fgh[fb][2*nt], fgh[fb][2*nt+1]);
        #pragma unroll
        for (int mt = 0; mt < 2; mt++)
            #pragma unroll
            for (int nt = 0; nt < 4; nt++)
                MMA16816(accu[mt][nt], fah[fb][mt], fuh[fb][2*nt], fuh[fb][2*nt+1]);
        #pragma unroll
        for (int mt = 0; mt < 2; mt++)
            #pragma unroll
            for (int nt = 0; nt < 4; nt++)
                MMA16816(accg[mt][nt], fah[fb][mt], fgl[fb][2*nt], fgl[fb][2*nt+1]);
        #pragma unroll
        for (int mt = 0; mt < 2; mt++)
            #pragma unroll
            for (int nt = 0; nt < 4; nt++)
                MMA16816(accu[mt][nt], fah[fb][mt], ful[fb][2*nt], ful[fb][2*nt+1]);
        #pragma unroll
        for (int mt = 0; mt < 2; mt++)
            #pragma unroll
            for (int nt = 0; nt < 4; nt++)
                MMA16816(accg[mt][nt], fal[fb][mt], fgh[fb][2*nt], fgh[fb][2*nt+1]);
        #pragma unroll
        for (int mt = 0; mt < 2; mt++)
            #pragma unroll
            for (int nt = 0; nt < 4; nt++)
                MMA16816(accu[mt][nt], fal[fb][mt], fuh[fb][2*nt], fuh[fb][2*nt+1]);
    };

    // prologue
    issueA(0, 0);
    loadB(0, pg, pu);
    storeB(0, pg, pu);
    CP_ASYNC_WAIT_ALL();
    __syncthreads();

    for (int s = 0; s < NS; s++) {
        const int b = s & 1;
        if (s + 1 < NS) { issueA(s + 1, b ^ 1); loadB(s + 1, pg, pu); }
        const uint32_t base = sb + b * GU_STAGE;
        ldfrag(base, 0, 0);
        #pragma unroll
        for (int k = 0; k < 4; k++) {
            if (k < 3) ldfrag(base, k + 1, (k + 1) & 1);
            mmafrag(k & 1);
        }
        if (s + 1 < NS) storeB(b ^ 1, pg, pu);
        CP_ASYNC_WAIT_ALL();
        __syncthreads();
    }

    // SwiGLU epilogue -> bf16 hi/lo
    const int g = lane >> 2, tig = lane & 3;
    #pragma unroll
    for (int mt = 0; mt < 2; mt++) {
        #pragma unroll
        for (int nt = 0; nt < 4; nt++) {
            int r1 = m0 + mw + mt*16 + g;
            int col = n0 + nw + nt*8 + 2*tig;
            {
                float gv0 = accg[mt][nt][0], gv1 = accg[mt][nt][1];
                float h0 = accu[mt][nt][0] * gv0 / (1.f + expf(-gv0));
                float h1 = accu[mt][nt][1] * gv1 / (1.f + expf(-gv1));
                uint32_t lo, hi = pack2(h0, h1, lo);
                *(uint32_t*)(Chi + (size_t)r1 * CLD + col) = hi;
                *(uint32_t*)(Clo + (size_t)r1 * CLD + col) = lo;
            }
            {
                float gv0 = accg[mt][nt][2], gv1 = accg[mt][nt][3];
                float h0 = accu[mt][nt][2] * gv0 / (1.f + expf(-gv0));
                float h1 = accu[mt][nt][3] * gv1 / (1.f + expf(-gv1));
                uint32_t lo, hi = pack2(h0, h1, lo);
                *(uint32_t*)(Chi + (size_t)(r1 + 8) * CLD + col) = hi;
                *(uint32_t*)(Clo + (size_t)(r1 + 8) * CLD + col) = lo;
            }
        }
    }
}

// ============ down GEMM (mma.sync bf16 3-pass), fragment-pipelined ============
// CTA 128x128, warp tile 64x32. ROUTED epilogue: weighted atomicAdd into out.
template<int ROUTED>
__global__ void __launch_bounds__(256)
dn_k(const __nv_bfloat16* __restrict__ Ah0, const __nv_bfloat16* __restrict__ Al0,
     const float* __restrict__ Bw0, float* __restrict__ C)
{
    constexpr int K  = ROUTED ? IM : ISH;
    constexpr int NS = K / BK;              // 22 or 44
    extern __shared__ char smem[];
    const uint32_t sb = smem_to_u32(smem);
    const int tid = threadIdx.x, wid = tid >> 5, lane = tid & 31;
    const int m0 = blockIdx.x * BM, n0 = blockIdx.y * 128;

    const float* bw = Bw0;
    if (ROUTED) {
        int e = d_tile_e[blockIdx.x];
        if (e < 0) return;
        bw += (size_t)e * HD * IM;
    }

    const int rb  = tid >> 3;
    const int chB = (tid & 7) * 16;
    const int chE = (tid & 7) * 8;
    uint32_t aswz[4];
    const __nv_bfloat16 *aah[4], *aal[4];
    #pragma unroll
    for (int i = 0; i < 4; i++) {
        int r = rb + i * 32;
        aswz[i] = SMEM_SWIZZLE_128B((uint32_t)(r * 128 + chB));
        aah[i] = Ah0 + (size_t)(m0 + r) * K + chE;
        aal[i] = Al0 + (size_t)(m0 + r) * K + chE;
    }
    const int brow_ld = tid >> 1;           // 0..127
    const int bc0     = (tid & 1) * 8;
    const float* bsrc = bw + (size_t)(n0 + brow_ld) * K + bc0 * 4;

    auto issueA = [&](int s, int buf) {
        const uint32_t bs = sb + (uint32_t)buf * DN_STAGE;
        #pragma unroll
        for (int i = 0; i < 4; i++) {
            CP_ASYNC16(bs + DN_AH + aswz[i], aah[i] + s * BK);
            CP_ASYNC16(bs + DN_AL + aswz[i], aal[i] + s * BK);
        }
    };
    auto loadB = [&](int s, float4* pb) {
        const float4* b4 = (const float4*)(bsrc + s * BK);
        #pragma unroll
        for (int j = 0; j < 8; j++) pb[j] = __ldg(b4 + j);
    };
    auto storeB = [&](int buf, const float4* pb) {
        char* bb = smem + (size_t)buf * DN_STAGE;
        #pragma unroll
        for (int j = 0; j < 4; j++)
            cvt_store8_reg(pb[2*j], pb[2*j+1], bb + DN_BH, bb + DN_BL, brow_ld, bc0 + 2*j);
    };

    // warp mapping: 2(m) x 4(n)
    const int mw = (wid & 1) * 64, nw = (wid >> 1) * 32;
    const int arow = mw + (lane & 15);
    const int acs  = lane >> 4;
    const int brow = nw + (lane & 7) + ((lane & 16) ? 8 : 0);
    const int bcs  = (lane >> 3) & 1;

    float acc[4][4][4] = {};
    float4 pb[8];

    uint32_t fah[2][4][4], fal[2][4][4], fbh[2][8], fbl[2][8];

    auto ldfrag = [&](uint32_t base, int k, int fb) {
        #pragma unroll
        for (int mt = 0; mt < 4; mt++) {
            uint32_t off = SMEM_SWIZZLE_128B((uint32_t)((arow + mt*16) * 128 + (2*k + acs) * 16));
            LDSM_X4(fah[fb][mt][0], fah[fb][mt][1], fah[fb][mt][2], fah[fb][mt][3], base + DN_AH + off);
            LDSM_X4(fal[fb][mt][0], fal[fb][mt][1], fal[fb][mt][2], fal[fb][mt][3], base + DN_AL + off);
        }
        uint32_t bo0 = SMEM_SWIZZLE_128B((uint32_t)(brow        * 128 + (2*k + bcs) * 16));
        uint32_t bo1 = SMEM_SWIZZLE_128B((uint32_t)((brow + 16) * 128 + (2*k + bcs) * 16));
        LDSM_X4(fbh[fb][0], fbh[fb][1], fbh[fb][2], fbh[fb][3], base + DN_BH + bo0);
        LDSM_X4(fbh[fb][4], fbh[fb][5], fbh[fb][6], fbh[fb][7], base + DN_BH + bo1);
        LDSM_X4(fbl[fb][0], fbl[fb][1], fbl[fb][2], fbl[fb][3], base + DN_BL + bo0);
        LDSM_X4(fbl[fb][4], fbl[fb][5], fbl[fb][6], fbl[fb][7], base + DN_BL + bo1);
    };
    auto mmafrag = [&](int fb) {
        #pragma unroll
        for (int mt = 0; mt < 4; mt++)
            #pragma unroll
            for (int nt = 0; nt < 4; nt++)
                MMA16816(acc[mt][nt], fah[fb][mt], fbh[fb][2*nt], fbh[fb][2*nt+1]);
        #pragma unroll
        for (int mt = 0; mt < 4; mt++)
            #pragma unroll
            for (int nt = 0; nt < 4; nt++)
                MMA16816(acc[mt][nt], fah[fb][mt], fbl[fb][2*nt], fbl[fb][2*nt+1]);
        #pragma unroll
        for (int mt = 0; mt < 4; mt++)
            #pragma unroll
            for (int nt = 0; nt < 4; nt++)
                MMA16816(acc[mt][nt], fal[fb][mt], fbh[fb][2*nt], fbh[fb][2*nt+1]);
    };

    issueA(0, 0);
    loadB(0, pb);
    storeB(0, pb);
    CP_ASYNC_WAIT_ALL();
    __syncthreads();

    for (int s = 0; s < NS; s++) {
        const int b = s & 1;
        if (s + 1 < NS) { issueA(s + 1, b ^ 1); loadB(s + 1, pb); }
        const uint32_t base = sb + b * DN_STAGE;
        ldfrag(base, 0, 0);
        #pragma unroll
        for (int k = 0; k < 4; k++) {
            if (k < 3) ldfrag(base, k + 1, (k + 1) & 1);
            mmafrag(k & 1);
        }
        if (s + 1 < NS) storeB(b ^ 1, pb);
        CP_ASYNC_WAIT_ALL();
        __syncthreads();
    }

    const int g = lane >> 2, tig = lane & 3;
    if (ROUTED) {
        // weighted scatter-accumulate into out (padding rows have w=0)
        #pragma unroll
        for (int mt = 0; mt < 4; mt++) {
            int r1 = m0 + mw + mt*16 + g;
            int t0 = d_ptok[r1];      float w0 = d_pw[r1];
            int t1 = d_ptok[r1 + 8];  float w1 = d_pw[r1 + 8];
            #pragma unroll
            for (int nt = 0; nt < 4; nt++) {
                int col = n0 + nw + nt*8 + 2*tig;
                atomicAdd(&C[(size_t)t0 * HD + col],     w0 * acc[mt][nt][0]);
                atomicAdd(&C[(size_t)t0 * HD + col + 1], w0 * acc[mt][nt][1]);
                atomicAdd(&C[(size_t)t1 * HD + col],     w1 * acc[mt][nt][2]);
                atomicAdd(&C[(size_t)t1 * HD + col + 1], w1 * acc[mt][nt][3]);
            }
        }
    } else {
        #pragma unroll
        for (int mt = 0; mt < 4; mt++) {
            #pragma unroll
            for (int nt = 0; nt < 4; nt++) {
                int r1 = m0 + mw + mt*16 + g;
                int col = n0 + nw + nt*8 + 2*tig;
                *(float2*)(C + (size_t)r1 * HD + col)       = make_float2(acc[mt][nt][0], acc[mt][nt][1]);
                *(float2*)(C + (size_t)(r1 + 8) * HD + col) = make_float2(acc[mt][nt][2], acc[mt][nt][3]);
            }
        }
    }
}

// ---------------- launch ----------------
extern "C" void kernel_launch(void* const* d_in, const int* in_sizes, int n_in,
                              void* d_out, int out_size)
{
    const float* x    = (const float*)d_in[0];
    const float* rw   = (const float*)d_in[1];
    const float* bias = (const float*)d_in[2];
    const float* gw   = (const float*)d_in[3];
    const float* uw   = (const float*)d_in[4];
    const float* dw   = (const float*)d_in[5];
    const float* sgw  = (const float*)d_in[6];
    const float* suw  = (const float*)d_in[7];
    const float* sdw  = (const float*)d_in[8];
    float* out = (float*)d_out;

    __nv_bfloat16 *xh, *xl, *hh, *hl, *shh, *shl;
    cudaGetSymbolAddress((void**)&xh,  x_hi);   cudaGetSymbolAddress((void**)&xl,  x_lo);
    cudaGetSymbolAddress((void**)&hh,  h_hi);   cudaGetSymbolAddress((void**)&hl,  h_lo);
    cudaGetSymbolAddress((void**)&shh, sh_hi);  cudaGetSymbolAddress((void**)&shl, sh_lo);

    cudaFuncSetAttribute(gu_k<1>, cudaFuncAttributeMaxDynamicSharedMemorySize, SMEM_BYTES);
    cudaFuncSetAttribute(gu_k<0>, cudaFuncAttributeMaxDynamicSharedMemorySize, SMEM_BYTES);
    cudaFuncSetAttribute(dn_k<1>, cudaFuncAttributeMaxDynamicSharedMemorySize, SMEM_BYTES);
    cudaFuncSetAttribute(dn_k<0>, cudaFuncAttributeMaxDynamicSharedMemorySize, SMEM_BYTES);

    split_k<<<512, 256>>>(x, xh, xl, (size_t)T*HD/4);
    router_k<<<T, 256>>>(x, rw, bias);
    build_pairs_k<<<1, 256>>>();

    // shared expert first (writes out), then routed accumulates atomically
    gu_k<0><<<dim3(T/BM, ISH/64),  256, SMEM_BYTES>>>(xh, xl, sgw, suw, shh, shl);
    dn_k<0><<<dim3(T/BM, HD/128),  256, SMEM_BYTES>>>(shh, shl, sdw, out);

    gu_k<1><<<dim3(NTILES, IM/64),  256, SMEM_BYTES>>>(xh, xl, gw, uw, hh, hl);
    dn_k<1><<<dim3(NTILES, HD/128), 256, SMEM_BYTES>>>(hh, hl, dw, out);
}

// round 15
// speedup vs baseline: 1.1138x; 1.1138x over previous
#include <cuda_runtime.h>
#include <cuda_bf16.h>
#include <cstdint>
#include <math.h>

// ---------------- problem constants ----------------
#define T     2048
#define HD    2048
#define E     8
#define IM    1408
#define ISH   2816
#define BM    128
#define BKF32 32            // bf16 k elems per stage (=64B rows, SW64)
#define MAXP  (2*T + E*BM)  // 5120
#define NTILES (MAXP/BM)    // 40

// gu stage layout (bytes): A hi/lo 8KB each, G hi/lo 2KB each, U hi/lo 2KB each
#define GU_AH 0
#define GU_AL 8192
#define GU_GH 16384
#define GU_GL 18432
#define GU_UH 20480
#define GU_UL 22528
#define GU_STAGE 24576
// dn stage layout: A hi/lo 8KB each, B hi/lo 4KB each
#define DN_AH 0
#define DN_AL 8192
#define DN_BH 16384
#define DN_BL 20480
#define DN_STAGE 24576
#define SMEM_BYTES (2*GU_STAGE)   // 49152

#define SWZ64(off) ((off) ^ (((off) >> 3) & 0x30))

__device__ __forceinline__ uint32_t smem_to_u32(const void* p) {
    uint32_t a;
    asm("{ .reg .u64 t; cvta.to.shared.u64 t, %1; cvt.u32.u64 %0, t; }" : "=r"(a) : "l"(p));
    return a;
}

#define CP_ASYNC16(dst_u32, src_ptr) \
    asm volatile("cp.async.cg.shared.global [%0], [%1], 16;" :: "r"(dst_u32), "l"(src_ptr))
#define CP_ASYNC_WAIT_ALL() asm volatile("cp.async.wait_all;" ::: "memory")

#define LDSM_X4(d0,d1,d2,d3,a) \
    asm volatile("ldmatrix.sync.aligned.m8n8.x4.shared.b16 {%0,%1,%2,%3}, [%4];" \
        : "=r"(d0), "=r"(d1), "=r"(d2), "=r"(d3) : "r"(a))

#define MMA16816(d, a, b0, b1) \
    asm volatile("mma.sync.aligned.m16n8k16.row.col.f32.bf16.bf16.f32 " \
        "{%0,%1,%2,%3}, {%4,%5,%6,%7}, {%8,%9}, {%0,%1,%2,%3};" \
        : "+f"((d)[0]), "+f"((d)[1]), "+f"((d)[2]), "+f"((d)[3]) \
        : "r"((a)[0]), "r"((a)[1]), "r"((a)[2]), "r"((a)[3]), "r"(b0), "r"(b1))

__device__ __forceinline__ uint32_t pack2(float x, float y, uint32_t& lob) {
    __nv_bfloat162 h = __float22bfloat162_rn(make_float2(x, y));
    float2 hf = __bfloat1622float2(h);
    __nv_bfloat162 l = __float22bfloat162_rn(make_float2(x - hf.x, y - hf.y));
    lob = *reinterpret_cast<uint32_t*>(&l);
    return *reinterpret_cast<uint32_t*>(&h);
}

// convert 8 fp32 (2 float4) -> one swizzled 16B hi + 16B lo store (64B rows)
__device__ __forceinline__ void cvt_store8_64(float4 a, float4 b, char* hibase, char* lobase,
                                              int row, int c16)
{
    uint32_t l0, l1, l2, l3;
    uint32_t h0 = pack2(a.x, a.y, l0);
    uint32_t h1 = pack2(a.z, a.w, l1);
    uint32_t h2 = pack2(b.x, b.y, l2);
    uint32_t h3 = pack2(b.z, b.w, l3);
    uint32_t sw = SWZ64((uint32_t)(row * 64 + c16 * 16));
    *(uint4*)(hibase + sw) = make_uint4(h0, h1, h2, h3);
    *(uint4*)(lobase + sw) = make_uint4(l0, l1, l2, l3);
}

// ---------------- device scratch ----------------
__device__ int   d_topk_idx[2*T];
__device__ float d_topk_w[2*T];
__device__ int   d_cnt[E];
__device__ int   d_off[E];
__device__ int   d_tile_e[NTILES];
__device__ int   d_ptok[MAXP];
__device__ float d_pw[MAXP];
__device__ __nv_bfloat16 x_hi[(size_t)T*HD],    x_lo[(size_t)T*HD];
__device__ __nv_bfloat16 h_hi[(size_t)MAXP*IM], h_lo[(size_t)MAXP*IM];
__device__ __nv_bfloat16 sh_hi[(size_t)T*ISH],  sh_lo[(size_t)T*ISH];

// ---------------- split x -> bf16 hi/lo ----------------
__global__ void split_k(const float* __restrict__ s,
                        __nv_bfloat16* __restrict__ hi, __nv_bfloat16* __restrict__ lo,
                        size_t n4)
{
    size_t stride = (size_t)gridDim.x * blockDim.x;
    const float4* s4 = (const float4*)s;
    uint2* h2 = (uint2*)hi;
    uint2* l2 = (uint2*)lo;
    for (size_t i = (size_t)blockIdx.x * blockDim.x + threadIdx.x; i < n4; i += stride) {
        float4 v = s4[i];
        uint32_t l0, l1;
        uint32_t h0 = pack2(v.x, v.y, l0);
        uint32_t h1 = pack2(v.z, v.w, l1);
        h2[i] = make_uint2(h0, h1);
        l2[i] = make_uint2(l0, l1);
    }
}

// ---------------- router ----------------
__global__ void router_k(const float* __restrict__ x,
                         const float* __restrict__ rw,
                         const float* __restrict__ bias)
{
    __shared__ float xs[HD];
    __shared__ float logits[E];
    int t = blockIdx.x, tid = threadIdx.x;
    for (int i = tid; i < HD; i += blockDim.x) xs[i] = x[(size_t)t*HD + i];
    __syncthreads();
    int wid = tid >> 5, lane = tid & 31;
    if (wid < E) {
        float s = 0.f;
        for (int k = lane; k < HD; k += 32) s += xs[k] * rw[wid*HD + k];
        #pragma unroll
        for (int o = 16; o; o >>= 1) s += __shfl_down_sync(0xffffffffu, s, o);
        if (!lane) logits[wid] = s;
    }
    __syncthreads();
    if (tid == 0) {
        float sc[E], sfc[E];
        #pragma unroll
        for (int e = 0; e < E; e++) {
            sc[e]  = 1.f / (1.f + expf(-logits[e]));
            sfc[e] = sc[e] + bias[e];
        }
        float gs[4];
        #pragma unroll
        for (int g = 0; g < 4; g++) gs[g] = sfc[2*g] + sfc[2*g+1];
        int g1 = 0;
        #pragma unroll
        for (int g = 1; g < 4; g++) if (gs[g] > gs[g1]) g1 = g;
        int g2 = -1;
        #pragma unroll
        for (int g = 0; g < 4; g++) { if (g == g1) continue; if (g2 < 0 || gs[g] > gs[g2]) g2 = g; }
        float masked[E];
        #pragma unroll
        for (int e = 0; e < E; e++) { int g = e >> 1; masked[e] = (g == g1 || g == g2) ? sfc[e] : 0.f; }
        int i1 = 0;
        #pragma unroll
        for (int e = 1; e < E; e++) if (masked[e] > masked[i1]) i1 = e;
        int i2 = -1;
        #pragma unroll
        for (int e = 0; e < E; e++) { if (e == i1) continue; if (i2 < 0 || masked[e] > masked[i2]) i2 = e; }
        float w1 = sc[i1], w2 = sc[i2];
        float inv = 2.5f / (w1 + w2 + 1e-20f);
        d_topk_idx[2*t] = i1; d_topk_idx[2*t+1] = i2;
        d_topk_w[2*t]   = w1 * inv;
        d_topk_w[2*t+1] = w2 * inv;
    }
}

// ---------------- deterministic pair list ----------------
__global__ void build_pairs_k()
{
    __shared__ int cnts[E], offs[E];
    int tid = threadIdx.x, wid = tid >> 5, lane = tid & 31;
    for (int i = tid; i < MAXP; i += blockDim.x) { d_ptok[i] = 0; d_pw[i] = 0.f; }
    if (wid < E) {
        int c = 0;
        for (int base = 0; base < T; base += 32) {
            int t = base + lane;
            bool sel = (d_topk_idx[2*t] == wid) || (d_topk_idx[2*t+1] == wid);
            c += __popc(__ballot_sync(0xffffffffu, sel));
        }
        if (!lane) cnts[wid] = c;
    }
    __syncthreads();
    if (tid == 0) {
        int o = 0;
        for (int e = 0; e < E; e++) {
            offs[e] = o; d_off[e] = o; d_cnt[e] = cnts[e];
            o += ((cnts[e] + BM - 1) / BM) * BM;
        }
        int tcur = 0;
        for (int e = 0; e < E; e++) {
            int t0 = offs[e] / BM, nt = (cnts[e] + BM - 1) / BM;
            for (int i = 0; i < nt; i++) d_tile_e[t0 + i] = e;
            tcur = t0 + nt;
        }
        for (int i = tcur; i < NTILES; i++) d_tile_e[i] = -1;
    }
    __syncthreads();
    if (wid < E) {
        int pos = offs[wid];
        for (int base = 0; base < T; base += 32) {
            int t = base + lane;
            int e0 = d_topk_idx[2*t], e1 = d_topk_idx[2*t+1];
            int j = (e0 == wid) ? 0 : ((e1 == wid) ? 1 : -1);
            unsigned m = __ballot_sync(0xffffffffu, j >= 0);
            if (j >= 0) {
                int p = pos + __popc(m & ((1u << lane) - 1u));
                d_ptok[p] = t;
                d_pw[p]   = d_topk_w[2*t+j];
            }
            pos += __popc(m);
        }
    }
}

// ============ fused gate+up GEMM, plane-split warps ============
// CTA tile 128(m) x 32(n), both planes. Warps 0-3: gate, 4-7: up (warp tile 32x32).
// SwiGLU pairing via smem exchange at end. 2 CTAs/SM.
template<int ROUTED>
__global__ void __launch_bounds__(256, 2)
gu_k(const __nv_bfloat16* __restrict__ Xh, const __nv_bfloat16* __restrict__ Xl,
     const float* __restrict__ Gw0, const float* __restrict__ Uw0,
     __nv_bfloat16* __restrict__ Chi, __nv_bfloat16* __restrict__ Clo)
{
    constexpr int NS  = HD / BKF32;         // 64
    constexpr int CLD = ROUTED ? IM : ISH;
    extern __shared__ char smem[];
    const uint32_t sb = smem_to_u32(smem);
    const int tid = threadIdx.x, wid = tid >> 5, lane = tid & 31;
    const int m0 = blockIdx.x * BM, n0 = blockIdx.y * 32;

    const float *gw = Gw0, *uw = Uw0;
    if (ROUTED) {
        int e = d_tile_e[blockIdx.x];
        if (e < 0) return;
        size_t eo = (size_t)e * IM * HD;
        gw += eo; uw += eo;
    }

    // A cp.async: thread handles rows (tid>>2) and (tid>>2)+64, 16B chunk (tid&3), hi+lo
    const int ar  = tid >> 2;               // 0..63
    const int ac  = tid & 3;
    uint32_t aswz0 = SWZ64((uint32_t)(ar * 64 + ac * 16));
    uint32_t aswz1 = SWZ64((uint32_t)((ar + 64) * 64 + ac * 16));
    int srow0, srow1;
    {
        int g0 = m0 + ar, g1 = m0 + ar + 64;
        srow0 = ROUTED ? d_ptok[g0] : g0;
        srow1 = ROUTED ? d_ptok[g1] : g1;
    }
    const __nv_bfloat16* axh0 = Xh + (size_t)srow0 * HD + ac * 8;
    const __nv_bfloat16* axl0 = Xl + (size_t)srow0 * HD + ac * 8;
    const __nv_bfloat16* axh1 = Xh + (size_t)srow1 * HD + ac * 8;
    const __nv_bfloat16* axl1 = Xl + (size_t)srow1 * HD + ac * 8;

    // B prefetch: threads 0-127 -> G, 128-255 -> U. row=(tid&127)>>2 (0..31), c16=tid&3, 8 fp32
    const int brow_ld = (tid & 127) >> 2;
    const float* bmat = (tid < 128) ? gw : uw;
    const float* bsrc = bmat + (size_t)(n0 + brow_ld) * HD + ac * 8;
    const int bh_off_st = (tid < 128) ? GU_GH : GU_UH;
    const int bl_off_st = (tid < 128) ? GU_GL : GU_UL;

    auto issueA = [&](int s, int buf) {
        const uint32_t bs = sb + (uint32_t)buf * GU_STAGE;
        CP_ASYNC16(bs + GU_AH + aswz0, axh0 + s * BKF32);
        CP_ASYNC16(bs + GU_AL + aswz0, axl0 + s * BKF32);
        CP_ASYNC16(bs + GU_AH + aswz1, axh1 + s * BKF32);
        CP_ASYNC16(bs + GU_AL + aswz1, axl1 + s * BKF32);
    };
    auto loadB = [&](int s, float4* pb) {
        const float4* b4 = (const float4*)(bsrc + s * BKF32);
        pb[0] = __ldg(b4); pb[1] = __ldg(b4 + 1);
    };
    auto storeB = [&](int buf, const float4* pb) {
        char* bb = smem + (size_t)buf * GU_STAGE;
        cvt_store8_64(pb[0], pb[1], bb + bh_off_st, bb + bl_off_st, brow_ld, ac);
    };

    // compute mapping: plane by warp group, warp tile 32(m) x 32(n)
    const bool isGate = (wid < 4);
    const int mw = (wid & 3) * 32;
    const int arow = mw + (lane & 15);
    const int acs  = lane >> 4;
    const int brow = (lane & 7) + ((lane & 16) ? 8 : 0);
    const int bcs  = (lane >> 3) & 1;
    const int bh_off = isGate ? GU_GH : GU_UH;
    const int bl_off = isGate ? GU_GL : GU_UL;

    float acc[2][4][4] = {};
    float4 pb[2];

    issueA(0, 0);
    loadB(0, pb);
    storeB(0, pb);
    CP_ASYNC_WAIT_ALL();
    __syncthreads();

    for (int s = 0; s < NS; s++) {
        const int b = s & 1;
        if (s + 1 < NS) { issueA(s + 1, b ^ 1); loadB(s + 1, pb); }
        const uint32_t base = sb + b * GU_STAGE;
        #pragma unroll
        for (int k = 0; k < 2; k++) {
            uint32_t ah[2][4], al[2][4], bh[8], bl[8];
            #pragma unroll
            for (int mt = 0; mt < 2; mt++) {
                uint32_t off = SWZ64((uint32_t)((arow + mt*16) * 64 + (2*k + acs) * 16));
                LDSM_X4(ah[mt][0], ah[mt][1], ah[mt][2], ah[mt][3], base + GU_AH + off);
                LDSM_X4(al[mt][0], al[mt][1], al[mt][2], al[mt][3], base + GU_AL + off);
            }
            uint32_t bo0 = SWZ64((uint32_t)(brow        * 64 + (2*k + bcs) * 16));
            uint32_t bo1 = SWZ64((uint32_t)((brow + 16) * 64 + (2*k + bcs) * 16));
            LDSM_X4(bh[0], bh[1], bh[2], bh[3], base + bh_off + bo0);
            LDSM_X4(bh[4], bh[5], bh[6], bh[7], base + bh_off + bo1);
            LDSM_X4(bl[0], bl[1], bl[2], bl[3], base + bl_off + bo0);
            LDSM_X4(bl[4], bl[5], bl[6], bl[7], base + bl_off + bo1);
            #pragma unroll
            for (int mt = 0; mt < 2; mt++)
                #pragma unroll
                for (int nt = 0; nt < 4; nt++) {
                    MMA16816(acc[mt][nt], ah[mt], bh[2*nt], bh[2*nt+1]);
                    MMA16816(acc[mt][nt], ah[mt], bl[2*nt], bl[2*nt+1]);
                    MMA16816(acc[mt][nt], al[mt], bh[2*nt], bh[2*nt+1]);
                }
        }
        if (s + 1 < NS) storeB(b ^ 1, pb);
        CP_ASYNC_WAIT_ALL();
        __syncthreads();
    }

    // exchange: gate warps store silu(g) to smem, up warps combine
    float* ex = (float*)smem;   // 4 warps * 32 lanes * 32 = 16KB < stage0
    const int exb = ((wid & 3) * 32 + lane) * 32;
    if (isGate) {
        #pragma unroll
        for (int mt = 0; mt < 2; mt++)
            #pragma unroll
            for (int nt = 0; nt < 4; nt++)
                #pragma unroll
                for (int q = 0; q < 4; q++) {
                    float gv = acc[mt][nt][q];
                    ex[exb + mt*16 + nt*4 + q] = gv / (1.f + expf(-gv));
                }
    }
    __syncthreads();
    if (!isGate) {
        const int g = lane >> 2, tig = lane & 3;
        #pragma unroll
        for (int mt = 0; mt < 2; mt++) {
            #pragma unroll
            for (int nt = 0; nt < 4; nt++) {
                float s0 = ex[exb + mt*16 + nt*4 + 0];
                float s1 = ex[exb + mt*16 + nt*4 + 1];
                float s2 = ex[exb + mt*16 + nt*4 + 2];
                float s3 = ex[exb + mt*16 + nt*4 + 3];
                float h0 = acc[mt][nt][0] * s0;
                float h1 = acc[mt][nt][1] * s1;
                float h2 = acc[mt][nt][2] * s2;
                float h3 = acc[mt][nt][3] * s3;
                int r1 = m0 + mw + mt*16 + g;
                int col = n0 + nt*8 + 2*tig;
                uint32_t lo, hi;
                hi = pack2(h0, h1, lo);
                *(uint32_t*)(Chi + (size_t)r1 * CLD + col) = hi;
                *(uint32_t*)(Clo + (size_t)r1 * CLD + col) = lo;
                hi = pack2(h2, h3, lo);
                *(uint32_t*)(Chi + (size_t)(r1 + 8) * CLD + col) = hi;
                *(uint32_t*)(Clo + (size_t)(r1 + 8) * CLD + col) = lo;
            }
        }
    }
}

// ============ down GEMM: CTA 128(m) x 64(n), warp tile 32x32, 2 CTAs/SM ============
template<int ROUTED>
__global__ void __launch_bounds__(256, 2)
dn_k(const __nv_bfloat16* __restrict__ Ah0, const __nv_bfloat16* __restrict__ Al0,
     const float* __restrict__ Bw0, float* __restrict__ C)
{
    constexpr int K  = ROUTED ? IM : ISH;
    constexpr int NS = K / BKF32;           // 44 or 88
    extern __shared__ char smem[];
    const uint32_t sb = smem_to_u32(smem);
    const int tid = threadIdx.x, wid = tid >> 5, lane = tid & 31;
    const int m0 = blockIdx.x * BM, n0 = blockIdx.y * 64;

    const float* bw = Bw0;
    if (ROUTED) {
        int e = d_tile_e[blockIdx.x];
        if (e < 0) return;
        bw += (size_t)e * HD * IM;
    }

    const int ar = tid >> 2;
    const int ac = tid & 3;
    uint32_t aswz0 = SWZ64((uint32_t)(ar * 64 + ac * 16));
    uint32_t aswz1 = SWZ64((uint32_t)((ar + 64) * 64 + ac * 16));
    const __nv_bfloat16* aah0 = Ah0 + (size_t)(m0 + ar) * K + ac * 8;
    const __nv_bfloat16* aal0 = Al0 + (size_t)(m0 + ar) * K + ac * 8;
    const __nv_bfloat16* aah1 = Ah0 + (size_t)(m0 + ar + 64) * K + ac * 8;
    const __nv_bfloat16* aal1 = Al0 + (size_t)(m0 + ar + 64) * K + ac * 8;

    // B prefetch: row = tid>>2 (0..63), c16 = tid&3, 8 fp32
    const float* bsrc = bw + (size_t)(n0 + ar) * K + ac * 8;

    auto issueA = [&](int s, int buf) {
        const uint32_t bs = sb + (uint32_t)buf * DN_STAGE;
        CP_ASYNC16(bs + DN_AH + aswz0, aah0 + s * BKF32);
        CP_ASYNC16(bs + DN_AL + aswz0, aal0 + s * BKF32);
        CP_ASYNC16(bs + DN_AH + aswz1, aah1 + s * BKF32);
        CP_ASYNC16(bs + DN_AL + aswz1, aal1 + s * BKF32);
    };
    auto loadB = [&](int s, float4* pb) {
        const float4* b4 = (const float4*)(bsrc + s * BKF32);
        pb[0] = __ldg(b4); pb[1] = __ldg(b4 + 1);
    };
    auto storeB = [&](int buf, const float4* pb) {
        char* bb = smem + (size_t)buf * DN_STAGE;
        cvt_store8_64(pb[0], pb[1], bb + DN_BH, bb + DN_BL, ar, ac);
    };

    // warp mapping: 4(m) x 2(n), warp tile 32x32
    const int mw = (wid & 3) * 32, nw = (wid >> 2) * 32;
    const int arow = mw + (lane & 15);
    const int acs  = lane >> 4;
    const int brow = nw + (lane & 7) + ((lane & 16) ? 8 : 0);
    const int bcs  = (lane >> 3) & 1;

    float acc[2][4][4] = {};
    float4 pb[2];

    issueA(0, 0);
    loadB(0, pb);
    storeB(0, pb);
    CP_ASYNC_WAIT_ALL();
    __syncthreads();

    for (int s = 0; s < NS; s++) {
        const int b = s & 1;
        if (s + 1 < NS) { issueA(s + 1, b ^ 1); loadB(s + 1, pb); }
        const uint32_t base = sb + b * DN_STAGE;
        #pragma unroll
        for (int k = 0; k < 2; k++) {
            uint32_t ah[2][4], al[2][4], bh[8], bl[8];
            #pragma unroll
            for (int mt = 0; mt < 2; mt++) {
                uint32_t off = SWZ64((uint32_t)((arow + mt*16) * 64 + (2*k + acs) * 16));
                LDSM_X4(ah[mt][0], ah[mt][1], ah[mt][2], ah[mt][3], base + DN_AH + off);
                LDSM_X4(al[mt][0], al[mt][1], al[mt][2], al[mt][3], base + DN_AL + off);
            }
            uint32_t bo0 = SWZ64((uint32_t)(brow        * 64 + (2*k + bcs) * 16));
            uint32_t bo1 = SWZ64((uint32_t)((brow + 16) * 64 + (2*k + bcs) * 16));
            LDSM_X4(bh[0], bh[1], bh[2], bh[3], base + DN_BH + bo0);
            LDSM_X4(bh[4], bh[5], bh[6], bh[7], base + DN_BH + bo1);
            LDSM_X4(bl[0], bl[1], bl[2], bl[3], base + DN_BL + bo0);
            LDSM_X4(bl[4], bl[5], bl[6], bl[7], base + DN_BL + bo1);
            #pragma unroll
            for (int mt = 0; mt < 2; mt++)
                #pragma unroll
                for (int nt = 0; nt < 4; nt++) {
                    MMA16816(acc[mt][nt], ah[mt], bh[2*nt], bh[2*nt+1]);
                    MMA16816(acc[mt][nt], ah[mt], bl[2*nt], bl[2*nt+1]);
                    MMA16816(acc[mt][nt], al[mt], bh[2*nt], bh[2*nt+1]);
                }
        }
        if (s + 1 < NS) storeB(b ^ 1, pb);
        CP_ASYNC_WAIT_ALL();
        __syncthreads();
    }

    const int g = lane >> 2, tig = lane & 3;
    if (ROUTED) {
        #pragma unroll
        for (int mt = 0; mt < 2; mt++) {
            int r1 = m0 + mw + mt*16 + g;
            int t0 = d_ptok[r1];      float w0 = d_pw[r1];
            int t1 = d_ptok[r1 + 8];  float w1 = d_pw[r1 + 8];
            #pragma unroll
            for (int nt = 0; nt < 4; nt++) {
                int col = n0 + nw + nt*8 + 2*tig;
                atomicAdd(&C[(size_t)t0 * HD + col],     w0 * acc[mt][nt][0]);
                atomicAdd(&C[(size_t)t0 * HD + col + 1], w0 * acc[mt][nt][1]);
                atomicAdd(&C[(size_t)t1 * HD + col],     w1 * acc[mt][nt][2]);
                atomicAdd(&C[(size_t)t1 * HD + col + 1], w1 * acc[mt][nt][3]);
            }
        }
    } else {
        #pragma unroll
        for (int mt = 0; mt < 2; mt++) {
            #pragma unroll
            for (int nt = 0; nt < 4; nt++) {
                int r1 = m0 + mw + mt*16 + g;
                int col = n0 + nw + nt*8 + 2*tig;
                *(float2*)(C + (size_t)r1 * HD + col)       = make_float2(acc[mt][nt][0], acc[mt][nt][1]);
                *(float2*)(C + (size_t)(r1 + 8) * HD + col) = make_float2(acc[mt][nt][2], acc[mt][nt][3]);
            }
        }
    }
}

// ---------------- launch ----------------
extern "C" void kernel_launch(void* const* d_in, const int* in_sizes, int n_in,
                              void* d_out, int out_size)
{
    const float* x    = (const float*)d_in[0];
    const float* rw   = (const float*)d_in[1];
    const float* bias = (const float*)d_in[2];
    const float* gw   = (const float*)d_in[3];
    const float* uw   = (const float*)d_in[4];
    const float* dw   = (const float*)d_in[5];
    const float* sgw  = (const float*)d_in[6];
    const float* suw  = (const float*)d_in[7];
    const float* sdw  = (const float*)d_in[8];
    float* out = (float*)d_out;

    __nv_bfloat16 *xh, *xl, *hh, *hl, *shh, *shl;
    cudaGetSymbolAddress((void**)&xh,  x_hi);   cudaGetSymbolAddress((void**)&xl,  x_lo);
    cudaGetSymbolAddress((void**)&hh,  h_hi);   cudaGetSymbolAddress((void**)&hl,  h_lo);
    cudaGetSymbolAddress((void**)&shh, sh_hi);  cudaGetSymbolAddress((void**)&shl, sh_lo);

    cudaFuncSetAttribute(gu_k<1>, cudaFuncAttributeMaxDynamicSharedMemorySize, SMEM_BYTES);
    cudaFuncSetAttribute(gu_k<0>, cudaFuncAttributeMaxDynamicSharedMemorySize, SMEM_BYTES);
    cudaFuncSetAttribute(dn_k<1>, cudaFuncAttributeMaxDynamicSharedMemorySize, SMEM_BYTES);
    cudaFuncSetAttribute(dn_k<0>, cudaFuncAttributeMaxDynamicSharedMemorySize, SMEM_BYTES);

    split_k<<<512, 256>>>(x, xh, xl, (size_t)T*HD/4);
    router_k<<<T, 256>>>(x, rw, bias);
    build_pairs_k<<<1, 256>>>();

    // shared expert first (writes out), then routed accumulates atomically
    gu_k<0><<<dim3(T/BM, ISH/32),  256, SMEM_BYTES>>>(xh, xl, sgw, suw, shh, shl);
    dn_k<0><<<dim3(T/BM, HD/64),   256, SMEM_BYTES>>>(shh, shl, sdw, out);

    gu_k<1><<<dim3(NTILES, IM/32), 256, SMEM_BYTES>>>(xh, xl, gw, uw, hh, hl);
    dn_k<1><<<dim3(NTILES, HD/64), 256, SMEM_BYTES>>>(hh, hl, dw, out);
}